// round 16
// baseline (speedup 1.0000x reference)
#include <cuda_runtime.h>
#include <cuda_bf16.h>
#include <cstdint>

#define BB 16
#define CC 128
#define HEAD 8
#define DKK 16
#define NNN 2500
#define LLL 12
#define NPOS (NNN*LLL)
#define TP 64
#define NT ((NPOS + TP - 1)/TP)      /* 469 */
#define NTILES (NT*BB)               /* 7504 */
#define TP2 128
#define NT2 ((NPOS + TP2 - 1)/TP2)   /* 235 */
#define NTILES2 (NT2*BB)             /* 3760 */
#define GRID_PERS 152
#define NTHR 512
#define VSP 132                      /* vsm pos-major pitch (floats) */

// ---------------- device scratch ----------------
__device__ __align__(16) uint4 g_WFH[3*2048];   // bf16 A-frags hi
__device__ __align__(16) uint4 g_WFL[3*2048];   // bf16 A-frags lo
__device__ __align__(16) float g_key[HEAD*LLL*NNN*DKK];
__device__ __align__(16) float g_kv[BB*LLL*HEAD*DKK*DKK];
__device__ __align__(16) float g_q[(size_t)BB*NPOS*CC];   // [b][p][c]
__device__ __align__(16) float g_o[(size_t)BB*NPOS*CC];   // [b][p][c]

// ---------------- helpers ----------------
__device__ __forceinline__ float rbf(float x) {
    return __bfloat162float(__float2bfloat16(x));
}
__device__ __forceinline__ uint32_t packbf(float vlo, float vhi) {
    uint32_t r;
    asm("cvt.rn.bf16x2.f32 %0, %1, %2;" : "=r"(r) : "f"(vhi), "f"(vlo));
    return r;
}
__device__ __forceinline__ void mma16(float d[4], const uint32_t a[4], uint32_t b0, uint32_t b1) {
    asm volatile("mma.sync.aligned.m16n8k16.row.col.f32.bf16.bf16.f32 "
        "{%0,%1,%2,%3}, {%4,%5,%6,%7}, {%8,%9}, {%0,%1,%2,%3};"
        : "+f"(d[0]), "+f"(d[1]), "+f"(d[2]), "+f"(d[3])
        : "r"(a[0]), "r"(a[1]), "r"(a[2]), "r"(a[3]), "r"(b0), "r"(b1));
}
__device__ __forceinline__ uint32_t smem_u32(const void* p) {
    uint32_t a;
    asm("{ .reg .u64 t; cvta.to.shared.u64 t, %1; cvt.u32.u64 %0, t; }" : "=r"(a) : "l"(p));
    return a;
}
#define CPASYNC16(dst_sa, src) \
    asm volatile("cp.async.cg.shared.global [%0], [%1], 16;" :: "r"(dst_sa), "l"(src) : "memory")
#define CPCOMMIT() asm volatile("cp.async.commit_group;" ::: "memory")
#define CPWAIT(n)  asm volatile("cp.async.wait_group %0;" :: "n"(n) : "memory")

// =======================================================================
// fused prep
// =======================================================================
#define KEY_BLOCKS ((HEAD*LLL*NNN + 255) / 256)          /* 938 */
#define ZKV_BLOCKS ((BB*LLL*HEAD*DKK*DKK/4) / 256)       /* 384 */
__global__ void k_prep(const float* __restrict__ Wq, const float* __restrict__ Wv,
                       const float* __restrict__ Wc, const float* __restrict__ s_bank) {
    int blk = blockIdx.x;
    if (blk < 3) {
        int w = blk;
        const float* src = (w == 0) ? Wq : (w == 1) ? Wv : Wc;
        for (int f = threadIdx.x; f < 2048; f += 256) {
            int lane = f & 31, chunk = (f >> 5) & 7, strip = (f >> 8) & 7;
            int g = lane >> 2, t = lane & 3;
            int m0 = strip * 16 + g, m1 = m0 + 8;
            int k0 = chunk * 16 + 2 * t;
            float w00 = src[m0*128 + k0],     w01 = src[m0*128 + k0 + 1];
            float w10 = src[m1*128 + k0],     w11 = src[m1*128 + k0 + 1];
            float w02 = src[m0*128 + k0 + 8], w03 = src[m0*128 + k0 + 9];
            float w12 = src[m1*128 + k0 + 8], w13 = src[m1*128 + k0 + 9];
            uint4 H, L;
            H.x = packbf(w00, w01); H.y = packbf(w10, w11);
            H.z = packbf(w02, w03); H.w = packbf(w12, w13);
            L.x = packbf(w00 - rbf(w00), w01 - rbf(w01));
            L.y = packbf(w10 - rbf(w10), w11 - rbf(w11));
            L.z = packbf(w02 - rbf(w02), w03 - rbf(w03));
            L.w = packbf(w12 - rbf(w12), w13 - rbf(w13));
            g_WFH[w*2048 + f] = H;
            g_WFL[w*2048 + f] = L;
        }
        return;
    }
    if (blk < 3 + KEY_BLOCKS) {
        int r = (blk - 3) * 256 + threadIdx.x;
        if (r >= HEAD*LLL*NNN) return;
        const float4* src = (const float4*)(s_bank + (size_t)r * 16);
        float4 v0 = src[0], v1 = src[1], v2 = src[2], v3 = src[3];
        float v[16] = {v0.x,v0.y,v0.z,v0.w, v1.x,v1.y,v1.z,v1.w,
                       v2.x,v2.y,v2.z,v2.w, v3.x,v3.y,v3.z,v3.w};
        float mx = v[0];
#pragma unroll
        for (int i = 1; i < 16; i++) mx = fmaxf(mx, v[i]);
        float s = 0.f;
#pragma unroll
        for (int i = 0; i < 16; i++) { v[i] = __expf(0.25f * (v[i] - mx)); s += v[i]; }
        float inv = 1.f / s;
#pragma unroll
        for (int i = 0; i < 16; i++) v[i] *= inv;
        float4* dst = (float4*)(g_key + (size_t)r * 16);
        dst[0] = make_float4(v[0],v[1],v[2],v[3]);
        dst[1] = make_float4(v[4],v[5],v[6],v[7]);
        dst[2] = make_float4(v[8],v[9],v[10],v[11]);
        dst[3] = make_float4(v[12],v[13],v[14],v[15]);
        return;
    }
    {
        int i = (blk - 3 - KEY_BLOCKS) * 256 + threadIdx.x;
        ((float4*)g_kv)[i] = make_float4(0.f, 0.f, 0.f, 0.f);
    }
}

// ---------------- QV staging (TP=64) ----------------
__device__ __forceinline__ void ldg_x(const float* __restrict__ xb, int pc, int tid,
                                      float vals[16]) {
#pragma unroll
    for (int k = 0; k < 4; k++) {
        int u = tid + k * 512;
        int lane = u & 31, chunk = (u >> 5) & 7, nt = u >> 8;
        int g = lane >> 2, t = lane & 3;
        int p = nt * 8 + g;
        int k0 = chunk * 16 + 2 * t;
        float v0 = 0.f, v1 = 0.f, v2 = 0.f, v3 = 0.f;
        if (p < pc) {
            v0 = __ldg(xb + (size_t)k0 * NPOS + p);
            v1 = __ldg(xb + (size_t)(k0 + 1) * NPOS + p);
            v2 = __ldg(xb + (size_t)(k0 + 8) * NPOS + p);
            v3 = __ldg(xb + (size_t)(k0 + 9) * NPOS + p);
        }
        vals[k*4+0] = v0; vals[k*4+1] = v1; vals[k*4+2] = v2; vals[k*4+3] = v3;
    }
}
__device__ __forceinline__ void sts_frag(uint4* frag, int tid, const float vals[16]) {
#pragma unroll
    for (int k = 0; k < 4; k++) {
        int u = tid + k * 512;
        float v0 = vals[k*4+0], v1 = vals[k*4+1], v2 = vals[k*4+2], v3 = vals[k*4+3];
        uint4 r;
        r.x = packbf(v0, v1);
        r.y = packbf(v2, v3);
        r.z = packbf(v0 - rbf(v0), v1 - rbf(v1));
        r.w = packbf(v2 - rbf(v2), v3 - rbf(v3));
        frag[u] = r;
    }
}

__device__ __forceinline__ void load_afrag(int w, int strip, int lane,
                                           uint32_t aH[8][4], uint32_t aL[8][4]) {
    const uint4* PH = g_WFH + w*2048 + strip*256 + lane;
    const uint4* PL = g_WFL + w*2048 + strip*256 + lane;
#pragma unroll
    for (int ch = 0; ch < 8; ch++) {
        uint4 h = __ldg(PH + ch*32);
        uint4 l = __ldg(PL + ch*32);
        aH[ch][0] = h.x; aH[ch][1] = h.y; aH[ch][2] = h.z; aH[ch][3] = h.w;
        aL[ch][0] = l.x; aL[ch][1] = l.y; aL[ch][2] = l.z; aL[ch][3] = l.w;
    }
}

// =======================================================================
// kernelQV: fused Q+V + kv accumulation (no g_v, no k_kv).
// smem: fbuf 64KB | weights 128KB | vsm 33.8KB = 230.4KB
// =======================================================================
#define SMEM_QV_BYTES (12288 * 16 + TP * VSP * 4)
__global__ void __launch_bounds__(NTHR, 1)
kernelQV(const float* __restrict__ x, const float* __restrict__ bq,
         const float* __restrict__ bv) {
    extern __shared__ uint4 sm[];
    uint4* fbuf = sm;              // 2 x 2048
    uint4* sWqH = sm + 4096;
    uint4* sWqL = sm + 6144;
    uint4* sWvH = sm + 8192;
    uint4* sWvL = sm + 10240;
    float* vsm  = (float*)(sm + 12288);   // [pos][ch] pitch VSP

    int tid = threadIdx.x, wid = tid >> 5, lane = tid & 31;
    int mg = wid & 7, nh = wid >> 3;
    int g = lane >> 2, t = lane & 3;
    int ch0 = mg * 16 + g;

    for (int i = tid; i < 2048; i += NTHR) {
        sWqH[i] = g_WFH[i];        sWqL[i] = g_WFL[i];
        sWvH[i] = g_WFH[2048 + i]; sWvL[i] = g_WFL[2048 + i];
    }
    float bqlo = __ldg(bq + ch0), bqhi = __ldg(bq + ch0 + 8);
    float bvlo = __ldg(bv + ch0), bvhi = __ldg(bv + ch0 + 8);

    // kv-phase roles: warp = (head, l-half)
    int hk = wid & 7, lh = wid >> 3;
    int xk = lane & 15, ybk = (lane >> 4) * 8;

    int tt0 = blockIdx.x;
    if (tt0 < NTILES) {
        int b = tt0 / NT, p0 = (tt0 % NT) * TP;
        int pc = min(TP, NPOS - p0);
        float vals[16];
        ldg_x(x + ((size_t)b * CC) * NPOS + p0, pc, tid, vals);
        sts_frag(fbuf, tid, vals);
    }
    __syncthreads();

    int cur = 0;
    for (int tt = tt0; tt < NTILES; tt += gridDim.x) {
        int b = tt / NT, p0 = (tt % NT) * TP;
        int pc = min(TP, NPOS - p0);

        int tn = tt + gridDim.x;
        float vals[16];
        bool have_next = (tn < NTILES);
        if (have_next) {
            int bn = tn / NT, p0n = (tn % NT) * TP;
            int pcn = min(TP, NPOS - p0n);
            ldg_x(x + ((size_t)bn * CC) * NPOS + p0n, pcn, tid, vals);
        }

        const uint4* frag = fbuf + cur * 2048;
        float dq[2][2][4], dv[2][2][4];
#pragma unroll
        for (int np = 0; np < 2; np++)
#pragma unroll
            for (int j = 0; j < 2; j++)
#pragma unroll
                for (int i = 0; i < 4; i++) { dq[np][j][i] = 0.f; dv[np][j][i] = 0.f; }

        const uint4* fb = frag + (nh * 4) * 256 + lane;
#pragma unroll 1
        for (int ch = 0; ch < 8; ch++) {
            int aidx = mg*256 + ch*32 + lane;
            uint4 qh = sWqH[aidx], ql = sWqL[aidx];
            uint4 vh = sWvH[aidx], vl = sWvL[aidx];
            uint32_t AQH[4] = {qh.x, qh.y, qh.z, qh.w};
            uint32_t AQL[4] = {ql.x, ql.y, ql.z, ql.w};
            uint32_t AVH[4] = {vh.x, vh.y, vh.z, vh.w};
            uint32_t AVL[4] = {vl.x, vl.y, vl.z, vl.w};
#pragma unroll
            for (int np = 0; np < 2; np++) {
                uint4 B0 = fb[np*512 + ch*32];
                uint4 B1 = fb[np*512 + 256 + ch*32];
                mma16(dq[np][0], AQH, B0.x, B0.y);
                mma16(dq[np][1], AQH, B1.x, B1.y);
                mma16(dv[np][0], AVH, B0.x, B0.y);
                mma16(dv[np][1], AVH, B1.x, B1.y);
                mma16(dq[np][0], AQL, B0.x, B0.y);
                mma16(dq[np][1], AQL, B1.x, B1.y);
                mma16(dv[np][0], AVL, B0.x, B0.y);
                mme:
                mma16(dv[np][1], AVL, B1.x, B1.y);
                mma16(dq[np][0], AQH, B0.z, B0.w);
                mma16(dq[np][1], AQH, B1.z, B1.w);
                mma16(dv[np][0], AVH, B0.z, B0.w);
                mma16(dv[np][1], AVH, B1.z, B1.w);
            }
        }

        // ---- Q epilogue ----
        float* qb = g_q + ((size_t)b * NPOS + p0) * CC;
#pragma unroll
        for (int np = 0; np < 2; np++) {
#pragma unroll
            for (int j = 0; j < 2; j++) {
                int c0 = (nh*4 + np*2 + j) * 8 + 2 * t;
                float v0 = fmaxf(dq[np][j][0] + bqlo, 0.f);
                float v1 = fmaxf(dq[np][j][1] + bqlo, 0.f);
                float v2 = fmaxf(dq[np][j][2] + bqhi, 0.f);
                float v3 = fmaxf(dq[np][j][3] + bqhi, 0.f);
                float me = fmaxf(v0, v2), mo = fmaxf(v1, v3);
#pragma unroll
                for (int o = 4; o < 32; o <<= 1) {
                    me = fmaxf(me, __shfl_xor_sync(0xffffffffu, me, o));
                    mo = fmaxf(mo, __shfl_xor_sync(0xffffffffu, mo, o));
                }
                float e0 = __expf(0.25f*(v0 - me)), e2 = __expf(0.25f*(v2 - me));
                float e1 = __expf(0.25f*(v1 - mo)), e3 = __expf(0.25f*(v3 - mo));
                float se = e0 + e2, so = e1 + e3;
#pragma unroll
                for (int o = 4; o < 32; o <<= 1) {
                    se += __shfl_xor_sync(0xffffffffu, se, o);
                    so += __shfl_xor_sync(0xffffffffu, so, o);
                }
                float ie = 1.f / se, io = 1.f / so;
                if (c0 < pc) {
                    qb[(size_t)c0 * CC + ch0]     = e0 * ie;
                    qb[(size_t)c0 * CC + ch0 + 8] = e2 * ie;
                }
                if (c0 + 1 < pc) {
                    qb[(size_t)(c0+1) * CC + ch0]     = e1 * io;
                    qb[(size_t)(c0+1) * CC + ch0 + 8] = e3 * io;
                }
            }
        }

        // ---- V epilogue -> vsm[pos][ch] ----
#pragma unroll
        for (int np = 0; np < 2; np++) {
#pragma unroll
            for (int j = 0; j < 2; j++) {
                int c0 = (nh*4 + np*2 + j) * 8 + 2 * t;
                vsm[c0 * VSP + ch0]           = fmaxf(dv[np][j][0] + bvlo, 0.f);
                vsm[c0 * VSP + ch0 + 8]       = fmaxf(dv[np][j][2] + bvhi, 0.f);
                vsm[(c0 + 1) * VSP + ch0]     = fmaxf(dv[np][j][1] + bvlo, 0.f);
                vsm[(c0 + 1) * VSP + ch0 + 8] = fmaxf(dv[np][j][3] + bvhi, 0.f);
            }
        }
        __syncthreads();   // vsm ready for all warps

        // ---- kv accumulation: warp = (head hk, l-half lh) ----
        {
            const float* keyh = g_key + ((size_t)hk * LLL) * NNN * DKK;
#pragma unroll 1
            for (int l = lh * 6; l < lh * 6 + 6; l++) {
                float a8[8];
#pragma unroll
                for (int j = 0; j < 8; j++) a8[j] = 0.f;
                int s = ((l - p0) % 12 + 12) % 12;
                for (int p = s; p < pc; p += 12) {
                    int n = (p0 + p) / 12;
                    float kx = __ldg(keyh + ((size_t)l * NNN + n) * DKK + xk);
                    const float4* vp = (const float4*)(vsm + p * VSP + hk * 16 + ybk);
                    float4 vA = vp[0], vB = vp[1];
                    a8[0] = fmaf(kx, vA.x, a8[0]); a8[1] = fmaf(kx, vA.y, a8[1]);
                    a8[2] = fmaf(kx, vA.z, a8[2]); a8[3] = fmaf(kx, vA.w, a8[3]);
                    a8[4] = fmaf(kx, vB.x, a8[4]); a8[5] = fmaf(kx, vB.y, a8[5]);
                    a8[6] = fmaf(kx, vB.z, a8[6]); a8[7] = fmaf(kx, vB.w, a8[7]);
                }
                float* kvp = g_kv + ((((size_t)b * LLL + l) * HEAD + hk) * DKK + xk) * DKK + ybk;
#pragma unroll
                for (int j = 0; j < 8; j++) atomicAdd(kvp + j, a8[j]);
            }
        }
        __syncthreads();   // vsm reads done

        if (have_next) sts_frag(fbuf + (cur ^ 1) * 2048, tid, vals);
        __syncthreads();
        cur ^= 1;
    }
}

// =======================================================================
// kernelB1: o[b,p,:] = q[b,p,:] @ kv[b,l(p)]  (R10 version)
// =======================================================================
#define B1_NPB 250
__global__ void __launch_bounds__(256, 2)
kernelB1() {
    int nc = blockIdx.x, l = blockIdx.y, b = blockIdx.z;
    int tid = threadIdx.x, wid = tid >> 5, lane = tid & 31;
    int h = lane >> 2, yq = lane & 3;

    const float* kvb = g_kv + (((size_t)b * LLL + l) * HEAD + h) * 256;
    float kvr[4][16];
#pragma unroll
    for (int xx = 0; xx < 16; xx++) {
        float4 kr = __ldg((const float4*)(kvb + xx * 16 + yq * 4));
        kvr[0][xx] = kr.x; kvr[1][xx] = kr.y; kvr[2][xx] = kr.z; kvr[3][xx] = kr.w;
    }

    int n0 = nc * B1_NPB;
    for (int i = wid; i < B1_NPB; i += 8) {
        int n = n0 + i;
        size_t P = (size_t)b * NPOS + (size_t)n * 12 + l;
        const float4* qr = (const float4*)(g_q + P * CC);
        float4 q0 = __ldg(qr + h * 4 + 0);
        float4 q1 = __ldg(qr + h * 4 + 1);
        float4 q2 = __ldg(qr + h * 4 + 2);
        float4 q3 = __ldg(qr + h * 4 + 3);
        float o0 = 0.f, o1 = 0.f, o2 = 0.f, o3 = 0.f;
#define B1ACC(qq, xb_) \
        o0 = fmaf(qq.x, kvr[0][xb_+0], o0); o1 = fmaf(qq.x, kvr[1][xb_+0], o1); \
        o2 = fmaf(qq.x, kvr[2][xb_+0], o2); o3 = fmaf(qq.x, kvr[3][xb_+0], o3); \
        o0 = fmaf(qq.y, kvr[0][xb_+1], o0); o1 = fmaf(qq.y, kvr[1][xb_+1], o1); \
        o2 = fmaf(qq.y, kvr[2][xb_+1], o2); o3 = fmaf(qq.y, kvr[3][xb_+1], o3); \
        o0 = fmaf(qq.z, kvr[0][xb_+2], o0); o1 = fmaf(qq.z, kvr[1][xb_+2], o1); \
        o2 = fmaf(qq.z, kvr[2][xb_+2], o2); o3 = fmaf(qq.z, kvr[3][xb_+2], o3); \
        o0 = fmaf(qq.w, kvr[0][xb_+3], o0); o1 = fmaf(qq.w, kvr[1][xb_+3], o1); \
        o2 = fmaf(qq.w, kvr[2][xb_+3], o2); o3 = fmaf(qq.w, kvr[3][xb_+3], o3);
        B1ACC(q0, 0) B1ACC(q1, 4) B1ACC(q2, 8) B1ACC(q3, 12)
#undef B1ACC
        ((float4*)(g_o + P * CC))[lane] = make_float4(o0, o1, o2, o3);
    }
}

// =======================================================================
// kernelB2 (R10): cp.async double-buffered raw o staging
// =======================================================================
#define SMEM_B2_BYTES (192 * 1024)
__global__ void __launch_bounds__(NTHR, 1)
kernelB2(const float* __restrict__ bc, float* __restrict__ out) {
    extern __shared__ float4 smB2[];
    float4* raw = smB2;                       // 2 x 4096 float4
    uint4* frag = (uint4*)(smB2 + 8192);      // 4096 uint4

    int tid = threadIdx.x, wid = tid >> 5, lane = tid & 31;
    int mg = wid & 7, nh = wid >> 3;
    int g = lane >> 2, t = lane & 3;
    int ch0 = mg * 16 + g;

    uint32_t aH[8][4], aL[8][4];
    load_afrag(2, mg, lane, aH, aL);
    float bclo = __ldg(bc + ch0), bchi = __ldg(bc + ch0 + 8);

    int tt0 = blockIdx.x;
    {
        int b = tt0 / NT2, p0 = (tt0 % NT2) * TP2;
        int pc = min(TP2, NPOS - p0);
        const float4* ob4 = (const float4*)(g_o + ((size_t)b * NPOS + p0) * CC);
#pragma unroll
        for (int k = 0; k < 8; k++) {
            int u = tid + k * 512;
            int p = u >> 5;
            if (p < pc) {
                CPASYNC16(smem_u32(raw + u), ob4 + u);
            } else {
                raw[u] = make_float4(0.f, 0.f, 0.f, 0.f);
            }
        }
        CPCOMMIT();
    }

    int cur = 0;
    for (int tt = tt0; tt < NTILES2; tt += gridDim.x) {
        int b = tt / NT2, p0 = (tt % NT2) * TP2;

        int tn = tt + gridDim.x;
        bool have_next = (tn < NTILES2);
        if (have_next) {
            int bn = tn / NT2, p0n = (tn % NT2) * TP2;
            int pcn = min(TP2, NPOS - p0n);
            const float4* ob4 = (const float4*)(g_o + ((size_t)bn * NPOS + p0n) * CC);
            float4* dst = raw + (cur ^ 1) * 4096;
#pragma unroll
            for (int k = 0; k < 8; k++) {
                int u = tid + k * 512;
                int p = u >> 5;
                if (p < pcn) {
                    CPASYNC16(smem_u32(dst + u), ob4 + u);
                } else {
                    dst[u] = make_float4(0.f, 0.f, 0.f, 0.f);
                }
            }
            CPCOMMIT();
            CPWAIT(1);
        } else {
            CPWAIT(0);
        }
        __syncthreads();

        const float2* rawf2 = (const float2*)(raw + cur * 4096);
#pragma unroll
        for (int k = 0; k < 8; k++) {
            int u = tid + k * 512;
            int lu = u & 31, chunk = (u >> 5) & 7, nt = u >> 8;
            int gu = lu >> 2, tu = lu & 3;
            int p = nt * 8 + gu;
            float2 rA = rawf2[p * 64 + chunk * 8 + tu];
            float2 rB = rawf2[p * 64 + chunk * 8 + tu + 4];
            uint4 r;
            r.x = packbf(rA.x, rA.y);
            r.y = packbf(rB.x, rB.y);
            r.z = packbf(rA.x - rbf(rA.x), rA.y - rbf(rA.y));
            r.w = packbf(rB.x - rbf(rB.x), rB.y - rbf(rB.y));
            frag[u] = r;
        }
        __syncthreads();

        int pc = min(TP2, NPOS - p0);
        float* ob = out + (size_t)b * CC * NPOS + p0;
#pragma unroll 1
        for (int ntp = 0; ntp < 4; ntp++) {
            int nt0 = nh * 8 + ntp * 2;
            const uint4* f0 = frag + nt0 * 256 + lane;
            const uint4* f1 = f0 + 256;
            float d[2][4];
#pragma unroll
            for (int j = 0; j < 2; j++)
#pragma unroll
                for (int i = 0; i < 4; i++) d[j][i] = 0.f;
#pragma unroll
            for (int ch = 0; ch < 8; ch++) {
                uint4 B0 = f0[ch*32];
                uint4 B1 = f1[ch*32];
                mma16(d[0], aH[ch], B0.x, B0.y);
                mma16(d[1], aH[ch], B1.x, B1.y);
                mma16(d[0], aL[ch], B0.x, B0.y);
                mma16(d[1], aL[ch], B1.x, B1.y);
                mma16(d[0], aH[ch], B0.z, B0.w);
                mma16(d[1], aH[ch], B1.z, B1.w);
            }
#pragma unroll
            for (int j = 0; j < 2; j++) {
                int c0 = (nt0 + j) * 8 + 2 * t;
                float w0 = fmaxf(d[j][0] + bclo, 0.f);
                float w1 = fmaxf(d[j][1] + bclo, 0.f);
                float w2 = fmaxf(d[j][2] + bchi, 0.f);
                float w3 = fmaxf(d[j][3] + bchi, 0.f);
                if (c0 + 1 < pc) {
                    *(float2*)(ob + (size_t)ch0 * NPOS + c0)       = make_float2(w0, w1);
                    *(float2*)(ob + (size_t)(ch0 + 8) * NPOS + c0) = make_float2(w2, w3);
                } else if (c0 < pc) {
                    ob[(size_t)ch0 * NPOS + c0]       = w0;
                    ob[(size_t)(ch0 + 8) * NPOS + c0] = w2;
                }
            }
        }
        __syncthreads();
        cur ^= 1;
    }
}

// ---------------- launch ----------------
extern "C" void kernel_launch(void* const* d_in, const int* in_sizes, int n_in,
                              void* d_out, int out_size) {
    (void)in_sizes; (void)n_in; (void)out_size;
    const float* x      = (const float*)d_in[0];
    const float* Wq     = (const float*)d_in[1];
    const float* bq     = (const float*)d_in[2];
    const float* Wv     = (const float*)d_in[3];
    const float* bv     = (const float*)d_in[4];
    const float* Wc     = (const float*)d_in[5];
    const float* bc     = (const float*)d_in[6];
    const float* s_bank = (const float*)d_in[7];
    float* out = (float*)d_out;

    cudaFuncSetAttribute(kernelQV, cudaFuncAttributeMaxDynamicSharedMemorySize, SMEM_QV_BYTES);
    cudaFuncSetAttribute(kernelB2, cudaFuncAttributeMaxDynamicSharedMemorySize, SMEM_B2_BYTES);

    k_prep<<<3 + KEY_BLOCKS + ZKV_BLOCKS, 256>>>(Wq, Wv, Wc, s_bank);
    kernelQV<<<GRID_PERS, NTHR, SMEM_QV_BYTES>>>(x, bq, bv);
    kernelB1<<<dim3(NNN/B1_NPB, LLL, BB), 256>>>();
    kernelB2<<<GRID_PERS, NTHR, SMEM_B2_BYTES>>>(bc, out);
}

// round 17
// speedup vs baseline: 2.1457x; 2.1457x over previous
#include <cuda_runtime.h>
#include <cuda_bf16.h>
#include <cstdint>

#define BB 16
#define CC 128
#define HEAD 8
#define DKK 16
#define NNN 2500
#define LLL 12
#define NPOS (NNN*LLL)
#define TP 64
#define NT ((NPOS + TP - 1)/TP)      /* 469 */
#define NTILES (NT*BB)               /* 7504 */
#define TP2 128
#define NT2 ((NPOS + TP2 - 1)/TP2)   /* 235 */
#define NTILES2 (NT2*BB)             /* 3760 */
#define GRID_PERS 152
#define NTHR 512

// ---------------- device scratch ----------------
__device__ __align__(16) uint4 g_WFH[3*2048];   // bf16 A-frags hi: [w][strip(8)][chunk(8)][lane(32)]
__device__ __align__(16) uint4 g_WFL[3*2048];   // bf16 A-frags lo
__device__ __align__(16) float g_key[HEAD*LLL*NNN*DKK];
__device__ __align__(16) float g_kv[BB*LLL*HEAD*DKK*DKK];
__device__ __align__(16) float g_q[(size_t)BB*NPOS*CC];   // [b][p][c]
__device__ __align__(16) float g_v[(size_t)BB*NPOS*CC];   // [b][p][c]
__device__ __align__(16) float g_o[(size_t)BB*NPOS*CC];   // [b][p][c]

// ---------------- helpers ----------------
__device__ __forceinline__ float rbf(float x) {
    return __bfloat162float(__float2bfloat16(x));
}
__device__ __forceinline__ uint32_t packbf(float vlo, float vhi) {
    uint32_t r;
    asm("cvt.rn.bf16x2.f32 %0, %1, %2;" : "=r"(r) : "f"(vhi), "f"(vlo));
    return r;
}
__device__ __forceinline__ void mma16(float d[4], const uint32_t a[4], uint32_t b0, uint32_t b1) {
    asm volatile("mma.sync.aligned.m16n8k16.row.col.f32.bf16.bf16.f32 "
        "{%0,%1,%2,%3}, {%4,%5,%6,%7}, {%8,%9}, {%0,%1,%2,%3};"
        : "+f"(d[0]), "+f"(d[1]), "+f"(d[2]), "+f"(d[3])
        : "r"(a[0]), "r"(a[1]), "r"(a[2]), "r"(a[3]), "r"(b0), "r"(b1));
}
__device__ __forceinline__ uint32_t smem_u32(const void* p) {
    uint32_t a;
    asm("{ .reg .u64 t; cvta.to.shared.u64 t, %1; cvt.u32.u64 %0, t; }" : "=r"(a) : "l"(p));
    return a;
}
#define CPASYNC16(dst_sa, src) \
    asm volatile("cp.async.cg.shared.global [%0], [%1], 16;" :: "r"(dst_sa), "l"(src) : "memory")
#define CPCOMMIT() asm volatile("cp.async.commit_group;" ::: "memory")
#define CPWAIT(n)  asm volatile("cp.async.wait_group %0;" :: "n"(n) : "memory")

// =======================================================================
// fused prep: blocks [0,3) = weight frags, [3, 3+938) = key softmax,
//             rest = zero kv
// =======================================================================
#define KEY_BLOCKS ((HEAD*LLL*NNN + 255) / 256)          /* 938 */
#define ZKV_BLOCKS ((BB*LLL*HEAD*DKK*DKK/4) / 256)       /* 384 */
__global__ void k_prep(const float* __restrict__ Wq, const float* __restrict__ Wv,
                       const float* __restrict__ Wc, const float* __restrict__ s_bank) {
    int blk = blockIdx.x;
    if (blk < 3) {
        int w = blk;
        const float* src = (w == 0) ? Wq : (w == 1) ? Wv : Wc;
        for (int f = threadIdx.x; f < 2048; f += 256) {
            int lane = f & 31, chunk = (f >> 5) & 7, strip = (f >> 8) & 7;
            int g = lane >> 2, t = lane & 3;
            int m0 = strip * 16 + g, m1 = m0 + 8;
            int k0 = chunk * 16 + 2 * t;
            float w00 = src[m0*128 + k0],     w01 = src[m0*128 + k0 + 1];
            float w10 = src[m1*128 + k0],     w11 = src[m1*128 + k0 + 1];
            float w02 = src[m0*128 + k0 + 8], w03 = src[m0*128 + k0 + 9];
            float w12 = src[m1*128 + k0 + 8], w13 = src[m1*128 + k0 + 9];
            uint4 H, L;
            H.x = packbf(w00, w01); H.y = packbf(w10, w11);
            H.z = packbf(w02, w03); H.w = packbf(w12, w13);
            L.x = packbf(w00 - rbf(w00), w01 - rbf(w01));
            L.y = packbf(w10 - rbf(w10), w11 - rbf(w11));
            L.z = packbf(w02 - rbf(w02), w03 - rbf(w03));
            L.w = packbf(w12 - rbf(w12), w13 - rbf(w13));
            g_WFH[w*2048 + f] = H;
            g_WFL[w*2048 + f] = L;
        }
        return;
    }
    if (blk < 3 + KEY_BLOCKS) {
        int r = (blk - 3) * 256 + threadIdx.x;
        if (r >= HEAD*LLL*NNN) return;
        const float4* src = (const float4*)(s_bank + (size_t)r * 16);
        float4 v0 = src[0], v1 = src[1], v2 = src[2], v3 = src[3];
        float v[16] = {v0.x,v0.y,v0.z,v0.w, v1.x,v1.y,v1.z,v1.w,
                       v2.x,v2.y,v2.z,v2.w, v3.x,v3.y,v3.z,v3.w};
        float mx = v[0];
#pragma unroll
        for (int i = 1; i < 16; i++) mx = fmaxf(mx, v[i]);
        float s = 0.f;
#pragma unroll
        for (int i = 0; i < 16; i++) { v[i] = __expf(0.25f * (v[i] - mx)); s += v[i]; }
        float inv = 1.f / s;
#pragma unroll
        for (int i = 0; i < 16; i++) v[i] *= inv;
        float4* dst = (float4*)(g_key + (size_t)r * 16);
        dst[0] = make_float4(v[0],v[1],v[2],v[3]);
        dst[1] = make_float4(v[4],v[5],v[6],v[7]);
        dst[2] = make_float4(v[8],v[9],v[10],v[11]);
        dst[3] = make_float4(v[12],v[13],v[14],v[15]);
        return;
    }
    {
        int i = (blk - 3 - KEY_BLOCKS) * 256 + threadIdx.x;
        ((float4*)g_kv)[i] = make_float4(0.f, 0.f, 0.f, 0.f);
    }
}

// ---------------- QV staging (TP=64): 2048 units/tile, 4 units/thread ----------------
__device__ __forceinline__ void ldg_x(const float* __restrict__ xb, int pc, int tid,
                                      float vals[16]) {
#pragma unroll
    for (int k = 0; k < 4; k++) {
        int u = tid + k * 512;
        int lane = u & 31, chunk = (u >> 5) & 7, nt = u >> 8;
        int g = lane >> 2, t = lane & 3;
        int p = nt * 8 + g;
        int k0 = chunk * 16 + 2 * t;
        float v0 = 0.f, v1 = 0.f, v2 = 0.f, v3 = 0.f;
        if (p < pc) {
            v0 = __ldg(xb + (size_t)k0 * NPOS + p);
            v1 = __ldg(xb + (size_t)(k0 + 1) * NPOS + p);
            v2 = __ldg(xb + (size_t)(k0 + 8) * NPOS + p);
            v3 = __ldg(xb + (size_t)(k0 + 9) * NPOS + p);
        }
        vals[k*4+0] = v0; vals[k*4+1] = v1; vals[k*4+2] = v2; vals[k*4+3] = v3;
    }
}
__device__ __forceinline__ void sts_frag(uint4* frag, int tid, const float vals[16]) {
#pragma unroll
    for (int k = 0; k < 4; k++) {
        int u = tid + k * 512;
        float v0 = vals[k*4+0], v1 = vals[k*4+1], v2 = vals[k*4+2], v3 = vals[k*4+3];
        uint4 r;
        r.x = packbf(v0, v1);
        r.y = packbf(v2, v3);
        r.z = packbf(v0 - rbf(v0), v1 - rbf(v1));
        r.w = packbf(v2 - rbf(v2), v3 - rbf(v3));
        frag[u] = r;
    }
}

// load A-frags for weight w, strip (16 rows) from GLOBAL into regs
__device__ __forceinline__ void load_afrag(int w, int strip, int lane,
                                           uint32_t aH[8][4], uint32_t aL[8][4]) {
    const uint4* PH = g_WFH + w*2048 + strip*256 + lane;
    const uint4* PL = g_WFL + w*2048 + strip*256 + lane;
#pragma unroll
    for (int ch = 0; ch < 8; ch++) {
        uint4 h = __ldg(PH + ch*32);
        uint4 l = __ldg(PL + ch*32);
        aH[ch][0] = h.x; aH[ch][1] = h.y; aH[ch][2] = h.z; aH[ch][3] = h.w;
        aL[ch][0] = l.x; aL[ch][1] = l.y; aL[ch][2] = l.z; aL[ch][3] = l.w;
    }
}

// =======================================================================
// kernelQV: fused Q+V, TP=64, reg-prefetch double-buffered pipeline (R10)
// =======================================================================
#define SMEM_QV_BYTES (12288 * 16)
__global__ void __launch_bounds__(NTHR, 1)
kernelQV(const float* __restrict__ x, const float* __restrict__ bq,
         const float* __restrict__ bv) {
    extern __shared__ uint4 sm[];
    uint4* fbuf = sm;              // 2 x 2048
    uint4* sWqH = sm + 4096;       // 2048 each
    uint4* sWqL = sm + 6144;
    uint4* sWvH = sm + 8192;
    uint4* sWvL = sm + 10240;

    int tid = threadIdx.x, wid = tid >> 5, lane = tid & 31;
    int mg = wid & 7, nh = wid >> 3;
    int g = lane >> 2, t = lane & 3;
    int ch0 = mg * 16 + g;

    for (int i = tid; i < 2048; i += NTHR) {
        sWqH[i] = g_WFH[i];        sWqL[i] = g_WFL[i];
        sWvH[i] = g_WFH[2048 + i]; sWvL[i] = g_WFL[2048 + i];
    }
    float bqlo = __ldg(bq + ch0), bqhi = __ldg(bq + ch0 + 8);
    float bvlo = __ldg(bv + ch0), bvhi = __ldg(bv + ch0 + 8);

    int tt0 = blockIdx.x;
    if (tt0 < NTILES) {
        int b = tt0 / NT, p0 = (tt0 % NT) * TP;
        int pc = min(TP, NPOS - p0);
        float vals[16];
        ldg_x(x + ((size_t)b * CC) * NPOS + p0, pc, tid, vals);
        sts_frag(fbuf, tid, vals);
    }
    __syncthreads();

    int cur = 0;
    for (int tt = tt0; tt < NTILES; tt += gridDim.x) {
        int b = tt / NT, p0 = (tt % NT) * TP;
        int pc = min(TP, NPOS - p0);

        int tn = tt + gridDim.x;
        float vals[16];
        bool have_next = (tn < NTILES);
        if (have_next) {
            int bn = tn / NT, p0n = (tn % NT) * TP;
            int pcn = min(TP, NPOS - p0n);
            ldg_x(x + ((size_t)bn * CC) * NPOS + p0n, pcn, tid, vals);
        }

        const uint4* frag = fbuf + cur * 2048;
        float dq[2][2][4], dv[2][2][4];
#pragma unroll
        for (int np = 0; np < 2; np++)
#pragma unroll
            for (int j = 0; j < 2; j++)
#pragma unroll
                for (int i = 0; i < 4; i++) { dq[np][j][i] = 0.f; dv[np][j][i] = 0.f; }

        const uint4* fb = frag + (nh * 4) * 256 + lane;
#pragma unroll 1
        for (int ch = 0; ch < 8; ch++) {
            int aidx = mg*256 + ch*32 + lane;
            uint4 qh = sWqH[aidx], ql = sWqL[aidx];
            uint4 vh = sWvH[aidx], vl = sWvL[aidx];
            uint32_t AQH[4] = {qh.x, qh.y, qh.z, qh.w};
            uint32_t AQL[4] = {ql.x, ql.y, ql.z, ql.w};
            uint32_t AVH[4] = {vh.x, vh.y, vh.z, vh.w};
            uint32_t AVL[4] = {vl.x, vl.y, vl.z, vl.w};
#pragma unroll
            for (int np = 0; np < 2; np++) {
                uint4 B0 = fb[np*512 + ch*32];
                uint4 B1 = fb[np*512 + 256 + ch*32];
                mma16(dq[np][0], AQH, B0.x, B0.y);
                mma16(dq[np][1], AQH, B1.x, B1.y);
                mma16(dv[np][0], AVH, B0.x, B0.y);
                mma16(dv[np][1], AVH, B1.x, B1.y);
                mma16(dq[np][0], AQL, B0.x, B0.y);
                mma16(dq[np][1], AQL, B1.x, B1.y);
                mma16(dv[np][0], AVL, B0.x, B0.y);
                mma16(dv[np][1], AVL, B1.x, B1.y);
                mma16(dq[np][0], AQH, B0.z, B0.w);
                mma16(dq[np][1], AQH, B1.z, B1.w);
                mma16(dv[np][0], AVH, B0.z, B0.w);
                mma16(dv[np][1], AVH, B1.z, B1.w);
            }
        }

        float* qb = g_q + ((size_t)b * NPOS + p0) * CC;
#pragma unroll
        for (int np = 0; np < 2; np++) {
#pragma unroll
            for (int j = 0; j < 2; j++) {
                int c0 = (nh*4 + np*2 + j) * 8 + 2 * t;
                float v0 = fmaxf(dq[np][j][0] + bqlo, 0.f);
                float v1 = fmaxf(dq[np][j][1] + bqlo, 0.f);
                float v2 = fmaxf(dq[np][j][2] + bqhi, 0.f);
                float v3 = fmaxf(dq[np][j][3] + bqhi, 0.f);
                float me = fmaxf(v0, v2), mo = fmaxf(v1, v3);
#pragma unroll
                for (int o = 4; o < 32; o <<= 1) {
                    me = fmaxf(me, __shfl_xor_sync(0xffffffffu, me, o));
                    mo = fmaxf(mo, __shfl_xor_sync(0xffffffffu, mo, o));
                }
                float e0 = __expf(0.25f*(v0 - me)), e2 = __expf(0.25f*(v2 - me));
                float e1 = __expf(0.25f*(v1 - mo)), e3 = __expf(0.25f*(v3 - mo));
                float se = e0 + e2, so = e1 + e3;
#pragma unroll
                for (int o = 4; o < 32; o <<= 1) {
                    se += __shfl_xor_sync(0xffffffffu, se, o);
                    so += __shfl_xor_sync(0xffffffffu, so, o);
                }
                float ie = 1.f / se, io = 1.f / so;
                if (c0 < pc) {
                    qb[(size_t)c0 * CC + ch0]     = e0 * ie;
                    qb[(size_t)c0 * CC + ch0 + 8] = e2 * ie;
                }
                if (c0 + 1 < pc) {
                    qb[(size_t)(c0+1) * CC + ch0]     = e1 * io;
                    qb[(size_t)(c0+1) * CC + ch0 + 8] = e3 * io;
                }
            }
        }

        float* vb = g_v + ((size_t)b * NPOS + p0) * CC;
#pragma unroll
        for (int np = 0; np < 2; np++) {
#pragma unroll
            for (int j = 0; j < 2; j++) {
                int c0 = (nh*4 + np*2 + j) * 8 + 2 * t;
                if (c0 < pc) {
                    vb[(size_t)c0 * CC + ch0]     = fmaxf(dv[np][j][0] + bvlo, 0.f);
                    vb[(size_t)c0 * CC + ch0 + 8] = fmaxf(dv[np][j][2] + bvhi, 0.f);
                }
                if (c0 + 1 < pc) {
                    vb[(size_t)(c0+1) * CC + ch0]     = fmaxf(dv[np][j][1] + bvlo, 0.f);
                    vb[(size_t)(c0+1) * CC + ch0 + 8] = fmaxf(dv[np][j][3] + bvhi, 0.f);
                }
            }
        }

        if (have_next) sts_frag(fbuf + (cur ^ 1) * 2048, tid, vals);
        __syncthreads();
        cur ^= 1;
    }
}

// =======================================================================
// k_kv: kv[b,l,h,x,y] += sum_n key[h,l,n,x] * v[b, n*12+l, h*16+y]
// =======================================================================
#define NCHUNK 250
__global__ void __launch_bounds__(256, 4)
k_kv() {
    int nc = blockIdx.x, l = blockIdx.y, b = blockIdx.z;
    int tid = threadIdx.x, wid = tid >> 5, lane = tid & 31;
    int h = wid;
    int xk = lane & 15, yb = (lane >> 4) * 8;
    int n0 = nc * NCHUNK;

    const float* keyh = g_key + (((size_t)h * LLL + l) * NNN) * DKK;
    const float* vbase = g_v + ((size_t)b * NPOS + l) * CC + h * 16 + yb;

    float acc[8];
#pragma unroll
    for (int j = 0; j < 8; j++) acc[j] = 0.f;

#pragma unroll 2
    for (int n = n0; n < n0 + NCHUNK; n++) {
        float kx = __ldg(keyh + (size_t)n * DKK + xk);
        const float4* vp = (const float4*)(vbase + (size_t)n * 12 * CC);
        float4 vA = __ldg(vp), vB = __ldg(vp + 1);
        acc[0] = fmaf(kx, vA.x, acc[0]); acc[1] = fmaf(kx, vA.y, acc[1]);
        acc[2] = fmaf(kx, vA.z, acc[2]); acc[3] = fmaf(kx, vA.w, acc[3]);
        acc[4] = fmaf(kx, vB.x, acc[4]); acc[5] = fmaf(kx, vB.y, acc[5]);
        acc[6] = fmaf(kx, vB.z, acc[6]); acc[7] = fmaf(kx, vB.w, acc[7]);
    }
    float* kvp = g_kv + ((((size_t)b * LLL + l) * HEAD + h) * DKK + xk) * DKK + yb;
#pragma unroll
    for (int j = 0; j < 8; j++) atomicAdd(kvp + j, acc[j]);
}

// =======================================================================
// kernelB1: o[b,p,:] = q[b,p,:] @ kv[b,l(p)]  (R10 version)
// =======================================================================
#define B1_NPB 250
__global__ void __launch_bounds__(256, 2)
kernelB1() {
    int nc = blockIdx.x, l = blockIdx.y, b = blockIdx.z;
    int tid = threadIdx.x, wid = tid >> 5, lane = tid & 31;
    int h = lane >> 2, yq = lane & 3;

    const float* kvb = g_kv + (((size_t)b * LLL + l) * HEAD + h) * 256;
    float kvr[4][16];
#pragma unroll
    for (int xx = 0; xx < 16; xx++) {
        float4 kr = __ldg((const float4*)(kvb + xx * 16 + yq * 4));
        kvr[0][xx] = kr.x; kvr[1][xx] = kr.y; kvr[2][xx] = kr.z; kvr[3][xx] = kr.w;
    }

    int n0 = nc * B1_NPB;
    for (int i = wid; i < B1_NPB; i += 8) {
        int n = n0 + i;
        size_t P = (size_t)b * NPOS + (size_t)n * 12 + l;
        const float4* qr = (const float4*)(g_q + P * CC);
        float4 q0 = __ldg(qr + h * 4 + 0);
        float4 q1 = __ldg(qr + h * 4 + 1);
        float4 q2 = __ldg(qr + h * 4 + 2);
        float4 q3 = __ldg(qr + h * 4 + 3);
        float o0 = 0.f, o1 = 0.f, o2 = 0.f, o3 = 0.f;
#define B1ACC(qq, xb_) \
        o0 = fmaf(qq.x, kvr[0][xb_+0], o0); o1 = fmaf(qq.x, kvr[1][xb_+0], o1); \
        o2 = fmaf(qq.x, kvr[2][xb_+0], o2); o3 = fmaf(qq.x, kvr[3][xb_+0], o3); \
        o0 = fmaf(qq.y, kvr[0][xb_+1], o0); o1 = fmaf(qq.y, kvr[1][xb_+1], o1); \
        o2 = fmaf(qq.y, kvr[2][xb_+1], o2); o3 = fmaf(qq.y, kvr[3][xb_+1], o3); \
        o0 = fmaf(qq.z, kvr[0][xb_+2], o0); o1 = fmaf(qq.z, kvr[1][xb_+2], o1); \
        o2 = fmaf(qq.z, kvr[2][xb_+2], o2); o3 = fmaf(qq.z, kvr[3][xb_+2], o3); \
        o0 = fmaf(qq.w, kvr[0][xb_+3], o0); o1 = fmaf(qq.w, kvr[1][xb_+3], o1); \
        o2 = fmaf(qq.w, kvr[2][xb_+3], o2); o3 = fmaf(qq.w, kvr[3][xb_+3], o3);
        B1ACC(q0, 0) B1ACC(q1, 4) B1ACC(q2, 8) B1ACC(q3, 12)
#undef B1ACC
        ((float4*)(g_o + P * CC))[lane] = make_float4(o0, o1, o2, o3);
    }
}

// =======================================================================
// kernelB2: out = relu(Wc o + bc) -> out[b][c][p]
// TP2=128, Wc A-frags in regs, cp.async double-buffered raw o staging (R10)
// =======================================================================
#define SMEM_B2_BYTES (192 * 1024)
__global__ void __launch_bounds__(NTHR, 1)
kernelB2(const float* __restrict__ bc, float* __restrict__ out) {
    extern __shared__ float4 smB2[];
    float4* raw = smB2;                       // 2 x 4096 float4
    uint4* frag = (uint4*)(smB2 + 8192);      // 4096 uint4

    int tid = threadIdx.x, wid = tid >> 5, lane = tid & 31;
    int mg = wid & 7, nh = wid >> 3;
    int g = lane >> 2, t = lane & 3;
    int ch0 = mg * 16 + g;

    uint32_t aH[8][4], aL[8][4];
    load_afrag(2, mg, lane, aH, aL);
    float bclo = __ldg(bc + ch0), bchi = __ldg(bc + ch0 + 8);

    int tt0 = blockIdx.x;
    {
        int b = tt0 / NT2, p0 = (tt0 % NT2) * TP2;
        int pc = min(TP2, NPOS - p0);
        const float4* ob4 = (const float4*)(g_o + ((size_t)b * NPOS + p0) * CC);
#pragma unroll
        for (int k = 0; k < 8; k++) {
            int u = tid + k * 512;
            int p = u >> 5;
            if (p < pc) {
                CPASYNC16(smem_u32(raw + u), ob4 + u);
            } else {
                raw[u] = make_float4(0.f, 0.f, 0.f, 0.f);
            }
        }
        CPCOMMIT();
    }

    int cur = 0;
    for (int tt = tt0; tt < NTILES2; tt += gridDim.x) {
        int b = tt / NT2, p0 = (tt % NT2) * TP2;

        int tn = tt + gridDim.x;
        bool have_next = (tn < NTILES2);
        if (have_next) {
            int bn = tn / NT2, p0n = (tn % NT2) * TP2;
            int pcn = min(TP2, NPOS - p0n);
            const float4* ob4 = (const float4*)(g_o + ((size_t)bn * NPOS + p0n) * CC);
            float4* dst = raw + (cur ^ 1) * 4096;
#pragma unroll
            for (int k = 0; k < 8; k++) {
                int u = tid + k * 512;
                int p = u >> 5;
                if (p < pcn) {
                    CPASYNC16(smem_u32(dst + u), ob4 + u);
                } else {
                    dst[u] = make_float4(0.f, 0.f, 0.f, 0.f);
                }
            }
            CPCOMMIT();
            CPWAIT(1);
        } else {
            CPWAIT(0);
        }
        __syncthreads();   // raw[cur] visible

        const float2* rawf2 = (const float2*)(raw + cur * 4096);
#pragma unroll
        for (int k = 0; k < 8; k++) {
            int u = tid + k * 512;
            int lu = u & 31, chunk = (u >> 5) & 7, nt = u >> 8;
            int gu = lu >> 2, tu = lu & 3;
            int p = nt * 8 + gu;
            float2 rA = rawf2[p * 64 + chunk * 8 + tu];
            float2 rB = rawf2[p * 64 + chunk * 8 + tu + 4];
            uint4 r;
            r.x = packbf(rA.x, rA.y);
            r.y = packbf(rB.x, rB.y);
            r.z = packbf(rA.x - rbf(rA.x), rA.y - rbf(rA.y));
            r.w = packbf(rB.x - rbf(rB.x), rB.y - rbf(rB.y));
            frag[u] = r;
        }
        __syncthreads();   // frag ready

        int pc = min(TP2, NPOS - p0);
        float* ob = out + (size_t)b * CC * NPOS + p0;
#pragma unroll 1
        for (int ntp = 0; ntp < 4; ntp++) {
            int nt0 = nh * 8 + ntp * 2;
            const uint4* f0 = frag + nt0 * 256 + lane;
            const uint4* f1 = f0 + 256;
            float d[2][4];
#pragma unroll
            for (int j = 0; j < 2; j++)
#pragma unroll
                for (int i = 0; i < 4; i++) d[j][i] = 0.f;
#pragma unroll
            for (int ch = 0; ch < 8; ch++) {
                uint4 B0 = f0[ch*32];
                uint4 B1 = f1[ch*32];
                mma16(d[0], aH[ch], B0.x, B0.y);
                mma16(d[1], aH[ch], B1.x, B1.y);
                mma16(d[0], aL[ch], B0.x, B0.y);
                mma16(d[1], aL[ch], B1.x, B1.y);
                mma16(d[0], aH[ch], B0.z, B0.w);
                mma16(d[1], aH[ch], B1.z, B1.w);
            }
#pragma unroll
            for (int j = 0; j < 2; j++) {
                int c0 = (nt0 + j) * 8 + 2 * t;
                float w0 = fmaxf(d[j][0] + bclo, 0.f);
                float w1 = fmaxf(d[j][1] + bclo, 0.f);
                float w2 = fmaxf(d[j][2] + bchi, 0.f);
                float w3 = fmaxf(d[j][3] + bchi, 0.f);
                if (c0 + 1 < pc) {
                    *(float2*)(ob + (size_t)ch0 * NPOS + c0)       = make_float2(w0, w1);
                    *(float2*)(ob + (size_t)(ch0 + 8) * NPOS + c0) = make_float2(w2, w3);
                } else if (c0 < pc) {
                    ob[(size_t)ch0 * NPOS + c0]       = w0;
                    ob[(size_t)(ch0 + 8) * NPOS + c0] = w2;
                }
            }
        }
        __syncthreads();   // frag free before next convert
        cur ^= 1;
    }
}

// ---------------- launch ----------------
extern "C" void kernel_launch(void* const* d_in, const int* in_sizes, int n_in,
                              void* d_out, int out_size) {
    (void)in_sizes; (void)n_in; (void)out_size;
    const float* x      = (const float*)d_in[0];
    const float* Wq     = (const float*)d_in[1];
    const float* bq     = (const float*)d_in[2];
    const float* Wv     = (const float*)d_in[3];
    const float* bv     = (const float*)d_in[4];
    const float* Wc     = (const float*)d_in[5];
    const float* bc     = (const float*)d_in[6];
    const float* s_bank = (const float*)d_in[7];
    float* out = (float*)d_out;

    cudaFuncSetAttribute(kernelQV, cudaFuncAttributeMaxDynamicSharedMemorySize, SMEM_QV_BYTES);
    cudaFuncSetAttribute(kernelB2, cudaFuncAttributeMaxDynamicSharedMemorySize, SMEM_B2_BYTES);

    k_prep<<<3 + KEY_BLOCKS + ZKV_BLOCKS, 256>>>(Wq, Wv, Wc, s_bank);
    kernelQV<<<GRID_PERS, NTHR, SMEM_QV_BYTES>>>(x, bq, bv);
    k_kv<<<dim3(NNN/NCHUNK, LLL, BB), 256>>>();
    kernelB1<<<dim3(NNN/B1_NPB, LLL, BB), 256>>>();
    kernelB2<<<GRID_PERS, NTHR, SMEM_B2_BYTES>>>(bc, out);
}